// round 12
// baseline (speedup 1.0000x reference)
#include <cuda_runtime.h>
#include <cuda_fp16.h>
#include <cstdint>
#include <math.h>

#define NTOK   49
#define CDIM   256
#define HEADS  8
#define HDIM   32
#define BWIN   4096
#define TOKS   (BWIN*NTOK)          // 200704 = 1568 * 128
#define KD     256                  // plain fp16
#define NITER  4                    // K/64
#define SCALE  0.17677669529663688f
#define LOG2E  1.4426950408889634f

// ---------------- scratch (device globals; no allocs) ----------------
__device__ __half g_A1[(size_t)TOKS*KD];   // fp16(x)   [t][256]
__device__ __half g_B1[512*KD];            // fp16(qkv_w)
__device__ __half g_B2[256*KD];            // fp16(proj_w)
// K and V tiles: [win][head] 64 tok-rows x 64B (32 fp16), swizzle key (tok>>1)&3. pads stay 0.
__device__ unsigned char g_Ks[(size_t)BWIN*HEADS*4096];
__device__ unsigned char g_Vt[(size_t)BWIN*HEADS*4096];
// Q fragments: [img][head][mtile 4][kind 2][lane 32] uint4 (pre-scaled by SCALE*LOG2E)
__device__ uint4  g_Qf[64*HEADS*4*2*32];
// bias in C-fragment layout, x LOG2E, mask folded: [head][mtile 4][ntile 7][lane 32] float4
__device__ float4 g_biasF[HEADS*4*7*32];

// ---------------- helpers ----------------
__device__ __forceinline__ uint32_t smem_u32(const void* p){
    uint32_t a;
    asm("{ .reg .u64 t; cvta.to.shared.u64 t, %1; cvt.u32.u64 %0, t; }" : "=r"(a) : "l"(p));
    return a;
}
__device__ __forceinline__ void cp_async16(uint32_t dst, const void* src){
    asm volatile("cp.async.cg.shared.global [%0], [%1], 16;" :: "r"(dst), "l"(src));
}
#define CP_COMMIT() asm volatile("cp.async.commit_group;")
#define CP_WAIT1()  asm volatile("cp.async.wait_group 1;")
#define CP_WAIT0()  asm volatile("cp.async.wait_group 0;")

__device__ __forceinline__ void ldmx4(uint32_t* r, uint32_t addr){
    asm volatile("ldmatrix.sync.aligned.m8n8.x4.shared.b16 {%0,%1,%2,%3}, [%4];"
        : "=r"(r[0]), "=r"(r[1]), "=r"(r[2]), "=r"(r[3]) : "r"(addr));
}
__device__ __forceinline__ void ldmx4t(uint32_t* r, uint32_t addr){
    asm volatile("ldmatrix.sync.aligned.m8n8.x4.trans.shared.b16 {%0,%1,%2,%3}, [%4];"
        : "=r"(r[0]), "=r"(r[1]), "=r"(r[2]), "=r"(r[3]) : "r"(addr));
}
__device__ __forceinline__ void mma16816(float* c, const uint32_t* a, const uint32_t* b){
    asm volatile("mma.sync.aligned.m16n8k16.row.col.f32.f16.f16.f32 "
        "{%0,%1,%2,%3}, {%4,%5,%6,%7}, {%8,%9}, {%0,%1,%2,%3};"
        : "+f"(c[0]), "+f"(c[1]), "+f"(c[2]), "+f"(c[3])
        : "r"(a[0]), "r"(a[1]), "r"(a[2]), "r"(a[3]), "r"(b[0]), "r"(b[1]));
}
__device__ __forceinline__ uint32_t pk2f(float a, float b){
    __half2 h = __floats2half2_rn(a, b);
    return *reinterpret_cast<uint32_t*>(&h);
}
__device__ __forceinline__ int rpi(int r, int c){
    int ai = r/7, aj = r%7, bi = c/7, bj = c%7;
    return (ai - bi + 6)*13 + (aj - bj + 6);
}

// ------- prep (weights, bias, Q frags) + conv_x merged, grid 4096x256 -------
__global__ void prep_conv(const float* __restrict__ qkv_w,
                          const float* __restrict__ proj_w,
                          const float* __restrict__ rbt,
                          const float* __restrict__ qg,
                          const float* __restrict__ x)
{
    int idx = blockIdx.x * 256 + threadIdx.x;
    if (idx < 512*256) g_B1[idx] = __float2half_rn(qkv_w[idx]);
    if (idx < 256*256) g_B2[idx] = __float2half_rn(proj_w[idx]);
    if (idx < HEADS*4*7*32) {
        int lane = idx & 31;
        int nt = (idx >> 5) % 7;
        int mt = (idx >> 5) / 7 % 4;
        int h  = idx / (32*7*4);
        int r0 = mt*16 + (lane>>2), r1 = r0 + 8;
        int c0 = nt*8 + 2*(lane&3), c1 = c0 + 1;
        float4 v;
        v.x = (r0 < 49 && c0 < 49) ? rbt[rpi(r0,c0)*HEADS + h]*LOG2E : -1e30f;
        v.y = (r0 < 49 && c1 < 49) ? rbt[rpi(r0,c1)*HEADS + h]*LOG2E : -1e30f;
        v.z = (r1 < 49 && c0 < 49) ? rbt[rpi(r1,c0)*HEADS + h]*LOG2E : -1e30f;
        v.w = (r1 < 49 && c1 < 49) ? rbt[rpi(r1,c1)*HEADS + h]*LOG2E : -1e30f;
        g_biasF[idx] = v;
    }
    if (idx < 64*HEADS*4*2*32) {   // Q fragments, pre-scaled by SCALE*LOG2E
        int lane = idx & 31;
        int kind = (idx >> 5) & 1;
        int mt   = (idx >> 6) & 3;
        int h    = (idx >> 8) & 7;
        int img  = idx >> 11;
        int r = mt*16 + (lane>>2);
        int c2 = 2*(lane&3);
        int db = kind * 16;
        const float qs = SCALE * LOG2E;
        auto qget = [&](int rr, int d) -> float {
            if (rr >= 49) return 0.f;
            return qg[(((size_t)img*HEADS + h)*NTOK + rr)*HDIM + d] * qs;
        };
        uint4 o;
        o.x = pk2f(qget(r,   db+c2),   qget(r,   db+c2+1));
        o.y = pk2f(qget(r+8, db+c2),   qget(r+8, db+c2+1));
        o.z = pk2f(qget(r,   db+c2+8), qget(r,   db+c2+9));
        o.w = pk2f(qget(r+8, db+c2+8), qget(r+8, db+c2+9));
        g_Qf[idx] = o;
    }
    // conv_x: grid-stride over TOKS*64 float4s
    {
        const float4* x4 = (const float4*)x;
        int stride = gridDim.x * 256;
        for (int i = idx; i < TOKS*64; i += stride) {
            float4 v = __ldg(x4 + i);
            *(uint2*)(g_A1 + (size_t)i*4) = make_uint2(pk2f(v.x, v.y), pk2f(v.z, v.w));
        }
    }
}

// ---------------- mma.sync fp16 GEMM1: KV = x @ qkv_w^T, K=256 -------------
#define GSTAGE 16384
#define GSMEM  (3*2*GSTAGE)    // 96 KB

__global__ void __launch_bounds__(256, 2)
gemm1_k(const float* __restrict__ bias)
{
    extern __shared__ char sm[];
    const __half* Ag = g_A1;
    const __half* Bg = g_B1;
    const int NOUT = 512;

    const int tid = threadIdx.x;
    const int n0 = blockIdx.x * 128;
    const int m0 = blockIdx.y * 128;
    const uint32_t sb = smem_u32(sm);

    auto load_stage = [&](int i, int s){
        const char* Abase = (const char*)Ag + ((size_t)m0*KD + (size_t)i*64)*2;
        const char* Bbase = (const char*)Bg + ((size_t)n0*KD + (size_t)i*64)*2;
        uint32_t sa  = sb + s*2*GSTAGE;
        uint32_t sbB = sa + GSTAGE;
        #pragma unroll
        for (int u = 0; u < 4; u++) {
            int idx = tid + u*256;
            int r = idx >> 3, c16 = idx & 7;
            uint32_t dst = (uint32_t)(r*128 + ((c16 ^ (r & 7))*16));
            cp_async16(sa  + dst, Abase + (size_t)r*(KD*2) + c16*16);
            cp_async16(sbB + dst, Bbase + (size_t)r*(KD*2) + c16*16);
        }
        CP_COMMIT();
    };

    const int w = tid >> 5, lane = tid & 31;
    const int wm = w >> 1, wn = w & 1;
    const int aRow = wm*32 + (lane & 15);
    const int aC16 = (lane >> 4);
    const int bRow = wn*64 + (lane & 7) + ((lane >> 4) << 3);
    const int bC16 = (lane >> 3) & 1;
    const int lc2 = 2*(lane & 3);

    float acc[2][8][4];
    #pragma unroll
    for (int mt = 0; mt < 2; mt++)
        #pragma unroll
        for (int nt = 0; nt < 8; nt++)
            #pragma unroll
            for (int q = 0; q < 4; q++) acc[mt][nt][q] = 0.f;

    load_stage(0, 0);
    load_stage(1, 1);
    int s = 0;
    for (int i = 0; i < NITER; i++) {
        if (i < NITER-1) { CP_WAIT1(); } else { CP_WAIT0(); }
        __syncthreads();
        if (i + 2 < NITER) {
            int s2 = s + 2; if (s2 >= 3) s2 -= 3;
            load_stage(i + 2, s2);
        }
        const uint32_t sa  = sb + s*2*GSTAGE;
        const uint32_t sbB = sa + GSTAGE;
        uint32_t af[4][2][4];
        #pragma unroll
        for (int kk = 0; kk < 4; kk++)
            #pragma unroll
            for (int mt = 0; mt < 2; mt++) {
                int r = aRow + mt*16, c = kk*2 + aC16;
                ldmx4(af[kk][mt], sa + r*128 + ((c ^ (r & 7))*16));
            }
        #pragma unroll
        for (int kk = 0; kk < 4; kk++) {
            #pragma unroll
            for (int np = 0; np < 4; np++) {
                uint32_t bf[4];
                int r = bRow + np*16, c = kk*2 + bC16;
                ldmx4(bf, sbB + r*128 + ((c ^ (r & 7))*16));
                #pragma unroll
                for (int mt = 0; mt < 2; mt++) {
                    mma16816(acc[mt][np*2+0], af[kk][mt], bf+0);
                    mma16816(acc[mt][np*2+1], af[kk][mt], bf+2);
                }
            }
        }
        if (++s >= 3) s -= 3;
    }

    // unified K/V epilogue: both hi-only tok-major 64B-row tiles, same swizzle
    const bool isK = (n0 + wn*64) < 256;
    char* arr = isK ? (char*)g_Ks : (char*)g_Vt;
    #pragma unroll
    for (int mt = 0; mt < 2; mt++) {
        int rowb = m0 + wm*32 + mt*16 + (lane >> 2);
        #pragma unroll
        for (int rr = 0; rr < 2; rr++) {
            int r = rowb + rr*8;
            int win = r / 49, tok = r - win*49;
            int key = (tok >> 1) & 3;
            char* base = arr + (size_t)win*(HEADS*4096) + (size_t)tok*64;
            #pragma unroll
            for (int nt = 0; nt < 8; nt++) {
                int gc = n0 + wn*64 + nt*8 + lc2;
                float v0 = acc[mt][nt][rr*2]   + __ldg(bias + gc);
                float v1 = acc[mt][nt][rr*2+1] + __ldg(bias + gc + 1);
                int c = gc & 255, head = c >> 5, d = c & 31;
                char* tb = base + head*4096;
                int chunk = d >> 3, inb = (2*d) & 15;
                *(uint32_t*)(tb + ((chunk ^ key)*16) + inb) = pk2f(v0, v1);
            }
        }
    }
}

// -------- tensor-core attention + fused proj (fp16, exp2, no max-pass) -----
// SMEM: [0,32K) K tiles ; [32K,64K) V tiles (later B2 double-buffer) ;
//       [64K,96K) attn-out stage: 4 kchunks x [64 rows x 128B], gemm-stage swizzle
#define A2OFF 65536
#define ASMEM (3*32768)   // 96KB
__global__ void __launch_bounds__(256, 2)
attn_k(const float* __restrict__ proj_b, float* __restrict__ out)
{
    extern __shared__ char sm[];
    const int tid = threadIdx.x, b = blockIdx.x;
    const uint32_t sb = smem_u32(sm);

    {   // stage K (group 0), then V (group 1); wait only for K here
        const char* srcK = (const char*)g_Ks + (size_t)b*32768;
        const char* srcV = (const char*)g_Vt + (size_t)b*32768;
        #pragma unroll
        for (int u = 0; u < 8; u++) {
            int i = tid + u*256;
            cp_async16(sb + i*16, srcK + i*16);
        }
        CP_COMMIT();
        #pragma unroll
        for (int u = 0; u < 8; u++) {
            int i = tid + u*256;
            cp_async16(sb + 32768 + i*16, srcV + i*16);
        }
        CP_COMMIT();
        CP_WAIT1();   // K arrived; V still in flight
    }
    __syncthreads();

    const int h = tid >> 5, lane = tid & 31;
    const int img = b >> 6;
    const uint32_t Kt = sb + h*4096;
    const uint32_t Vt = sb + 32768 + h*4096;
    const int lr = lane >> 2, lc2 = 2*(lane & 3);
    const int brow = (lane & 7) + ((lane >> 4) << 3);
    const int bch  = (lane >> 3) & 1;
    const int vrow = lane & 15;
    const int vch  = lane >> 4;

    const uint4*  qf = g_Qf    + ((size_t)(img*HEADS + h)*8)*32 + lane;
    const float4* bf = g_biasF + ((size_t)h*4*7)*32 + lane;

    for (int mt = 0; mt < 4; mt++) {
        uint32_t af[2][4];
        #pragma unroll
        for (int kd = 0; kd < 2; kd++) {
            uint4 v = __ldg(qf + (mt*2 + kd)*32);
            af[kd][0]=v.x; af[kd][1]=v.y; af[kd][2]=v.z; af[kd][3]=v.w;
        }
        float s[8][4];
        #pragma unroll
        for (int nt = 0; nt < 8; nt++)
            #pragma unroll
            for (int j = 0; j < 4; j++) s[nt][j] = 0.f;

        // QK^T in log2 domain (Q pre-scaled by SCALE*log2e)
        #pragma unroll
        for (int np = 0; np < 4; np++) {
            uint32_t kb[2][4];
            int row = np*16 + brow;
            int key = (row >> 1) & 3;
            #pragma unroll
            for (int ch = 0; ch < 2; ch++) {
                int chunk = ch*2 + bch;
                ldmx4(kb[ch], Kt + row*64 + ((chunk ^ key)*16));
            }
            float* s0 = s[2*np]; float* s1 = s[2*np+1];
            mma16816(s0, af[0], kb[0]+0); mma16816(s1, af[0], kb[0]+2);
            mma16816(s0, af[1], kb[1]+0); mma16816(s1, af[1], kb[1]+2);
        }

        // softmax (no max-pass; scores bounded); p = exp2(s + bias2)
        float den0 = 0.f, den1 = 0.f;
        #pragma unroll
        for (int nt = 0; nt < 7; nt++) {
            float4 t = __ldg(bf + (mt*7 + nt)*32);
            s[nt][0] = exp2f(s[nt][0] + t.x); den0 += s[nt][0];
            s[nt][1] = exp2f(s[nt][1] + t.y); den0 += s[nt][1];
            s[nt][2] = exp2f(s[nt][2] + t.z); den1 += s[nt][2];
            s[nt][3] = exp2f(s[nt][3] + t.w); den1 += s[nt][3];
        }
        den0 += __shfl_xor_sync(0xFFFFFFFF, den0, 1);
        den0 += __shfl_xor_sync(0xFFFFFFFF, den0, 2);
        den1 += __shfl_xor_sync(0xFFFFFFFF, den1, 1);
        den1 += __shfl_xor_sync(0xFFFFFFFF, den1, 2);

        // P -> A fragments (fp16, packed cvt)
        uint32_t ph[4][4];
        #pragma unroll
        for (int ks = 0; ks < 4; ks++) {
            #pragma unroll
            for (int half_ = 0; half_ < 2; half_++) {
                int nt = 2*ks + half_;
                if (nt < 7) {
                    ph[ks][half_*2+0] = pk2f(s[nt][0], s[nt][1]);
                    ph[ks][half_*2+1] = pk2f(s[nt][2], s[nt][3]);
                } else {
                    ph[ks][half_*2] = 0; ph[ks][half_*2+1] = 0;
                }
            }
        }

        // before first PV, make sure V staging landed
        if (mt == 0) { CP_WAIT0(); __syncthreads(); }

        // PV: p x v, V via ldmatrix.trans from tok-major tiles
        float o[4][4];
        #pragma unroll
        for (int nt = 0; nt < 4; nt++)
            #pragma unroll
            for (int j = 0; j < 4; j++) o[nt][j] = 0.f;
        #pragma unroll
        for (int ks = 0; ks < 4; ks++) {
            int row = ks*16 + vrow;
            int key = (row >> 1) & 3;
            #pragma unroll
            for (int nh = 0; nh < 2; nh++) {
                uint32_t vh[4];
                int chunk = nh*2 + vch;
                ldmx4t(vh, Vt + row*64 + ((chunk ^ key)*16));
                mma16816(o[2*nh+0], ph[ks], vh+0);
                mma16816(o[2*nh+1], ph[ks], vh+2);
            }
        }

        // store attn-out to SMEM A2 stage (gemm-fragment layout, zeros for pad rows)
        int r0 = mt*16 + lr, r1 = r0 + 8;
        float ri0 = (r0 < 49) ? (1.f/den0) : 0.f;
        float ri1 = (r1 < 49) ? (1.f/den1) : 0.f;
        #pragma unroll
        for (int nt = 0; nt < 4; nt++) {
            int gc = h*HDIM + nt*8 + lc2;                   // 0..255
            int kc = gc >> 6, cc = gc & 63;
            uint32_t basea = A2OFF + kc*8192 + ((2*cc) & 15);
            *(uint32_t*)(sm + basea + r0*128 + (((cc>>3) ^ (r0 & 7))*16))
                = pk2f(o[nt][0]*ri0, o[nt][1]*ri0);
            *(uint32_t*)(sm + basea + r1*128 + (((cc>>3) ^ (r1 & 7))*16))
                = pk2f(o[nt][2]*ri1, o[nt][3]*ri1);
        }
    }

    // ===================== fused proj: out = A2 @ B2^T + b ==================
    __syncthreads();    // attn done everywhere; K/V smem free

    auto load_b2 = [&](int j){
        uint32_t base = sb + (j & 1)*32768;
        const char* src = (const char*)g_B2 + (size_t)j*64*512;  // 64 rows x 512B
        #pragma unroll
        for (int u = 0; u < 8; u++) {
            int idx = tid + u*256;         // 0..2047 16B chunks
            int r = idx >> 5, c16 = idx & 31;
            int kc = c16 >> 3, cw = c16 & 7;
            cp_async16(base + kc*8192 + r*128 + ((cw ^ (r & 7))*16),
                       src + (size_t)r*512 + c16*16);
        }
        CP_COMMIT();
    };
    load_b2(0);
    load_b2(1);

    const int wm = h >> 2, wn = h & 3;       // 2 x 4 warp grid
    const int aRowp = wm*32 + (lane & 15);
    const int aC16p = lane >> 4;
    const int bRowp = wn*16 + (lane & 7) + ((lane >> 4) << 3);
    const int bC16p = (lane >> 3) & 1;

    for (int j = 0; j < 4; j++) {
        if (j < 3) { CP_WAIT1(); } else { CP_WAIT0(); }
        __syncthreads();
        const uint32_t bbuf = sb + (j & 1)*32768;

        float pacc[2][2][4];
        #pragma unroll
        for (int m2 = 0; m2 < 2; m2++)
            #pragma unroll
            for (int n2 = 0; n2 < 2; n2++)
                #pragma unroll
                for (int q = 0; q < 4; q++) pacc[m2][n2][q] = 0.f;

        #pragma unroll
        for (int kc = 0; kc < 4; kc++) {
            #pragma unroll
            for (int kk = 0; kk < 4; kk++) {
                uint32_t paf[2][4];
                #pragma unroll
                for (int m2 = 0; m2 < 2; m2++) {
                    int r = aRowp + m2*16, c = kk*2 + aC16p;
                    ldmx4(paf[m2], sb + A2OFF + kc*8192 + r*128 + ((c ^ (r & 7))*16));
                }
                uint32_t pbf[4];
                int cb = kk*2 + bC16p;
                ldmx4(pbf, bbuf + kc*8192 + bRowp*128 + ((cb ^ (bRowp & 7))*16));
                #pragma unroll
                for (int m2 = 0; m2 < 2; m2++) {
                    mma16816(pacc[m2][0], paf[m2], pbf+0);
                    mma16816(pacc[m2][1], paf[m2], pbf+2);
                }
            }
        }

        // epilogue for this n-chunk
        #pragma unroll
        for (int n2 = 0; n2 < 2; n2++) {
            int col = j*64 + wn*16 + n2*8 + lc2;
            float bx = __ldg(proj_b + col), by = __ldg(proj_b + col + 1);
            #pragma unroll
            for (int m2 = 0; m2 < 2; m2++) {
                int row = wm*32 + m2*16 + lr;
                if (row < 49)
                    *(float2*)(out + ((size_t)b*NTOK + row)*256 + col)
                        = make_float2(pacc[m2][n2][0] + bx, pacc[m2][n2][1] + by);
                if (row + 8 < 49)
                    *(float2*)(out + ((size_t)b*NTOK + row + 8)*256 + col)
                        = make_float2(pacc[m2][n2][2] + bx, pacc[m2][n2][3] + by);
            }
        }

        __syncthreads();                 // all warps done with buffer (j&1)
        if (j + 2 < 4) load_b2(j + 2);
    }
}

// ---------------- launch ----------------
extern "C" void kernel_launch(void* const* d_in, const int* in_sizes, int n_in,
                              void* d_out, int out_size)
{
    const float* x      = (const float*)d_in[0];
    const float* qg     = (const float*)d_in[1];
    const float* qkv_w  = (const float*)d_in[2];
    const float* qkv_b  = (const float*)d_in[3];
    const float* proj_w = (const float*)d_in[4];
    const float* proj_b = (const float*)d_in[5];
    const float* rbt    = (const float*)d_in[6];
    float* out = (float*)d_out;
    (void)in_sizes; (void)n_in; (void)out_size;

    cudaFuncSetAttribute(gemm1_k, cudaFuncAttributeMaxDynamicSharedMemorySize, GSMEM);
    cudaFuncSetAttribute(attn_k,  cudaFuncAttributeMaxDynamicSharedMemorySize, ASMEM);

    prep_conv<<<4096, 256>>>(qkv_w, proj_w, rbt, qg, x);
    {
        dim3 g1(4, TOKS/128);
        gemm1_k<<<g1, 256, GSMEM>>>(qkv_b);
    }
    attn_k<<<BWIN, 256, ASMEM>>>(proj_b, out);
}

// round 13
// speedup vs baseline: 1.0647x; 1.0647x over previous
#include <cuda_runtime.h>
#include <cuda_fp16.h>
#include <cstdint>
#include <math.h>

#define NTOK   49
#define CDIM   256
#define HEADS  8
#define HDIM   32
#define BWIN   4096
#define TOKS   (BWIN*NTOK)          // 200704 = 1568 * 128
#define KD     256                  // plain fp16
#define NITER  4                    // K/64
#define SCALE  0.17677669529663688f
#define LOG2E  1.4426950408889634f

// ---------------- scratch (device globals; no allocs) ----------------
__device__ __half g_A1[(size_t)TOKS*KD];   // fp16(x)   [t][256]
__device__ __half g_A2[(size_t)TOKS*KD];   // attn-out  [t][256]
__device__ __half g_B1[512*KD];            // fp16(qkv_w)
__device__ __half g_B2[256*KD];            // fp16(proj_w)
// K and V tiles: [win][head] 64 tok-rows x 64B (32 fp16), swizzle key (tok>>1)&3. pads stay 0.
__device__ unsigned char g_Ks[(size_t)BWIN*HEADS*4096];
__device__ unsigned char g_Vt[(size_t)BWIN*HEADS*4096];
// Q fragments: [img][head][mtile 4][kind 2][lane 32] uint4 (pre-scaled by SCALE*LOG2E)
__device__ uint4  g_Qf[64*HEADS*4*2*32];
// bias in C-fragment layout, x LOG2E, mask folded: [head][mtile 4][ntile 7][lane 32] float4
__device__ float4 g_biasF[HEADS*4*7*32];

// ---------------- helpers ----------------
__device__ __forceinline__ uint32_t smem_u32(const void* p){
    uint32_t a;
    asm("{ .reg .u64 t; cvta.to.shared.u64 t, %1; cvt.u32.u64 %0, t; }" : "=r"(a) : "l"(p));
    return a;
}
__device__ __forceinline__ void cp_async16(uint32_t dst, const void* src){
    asm volatile("cp.async.cg.shared.global [%0], [%1], 16;" :: "r"(dst), "l"(src));
}
#define CP_COMMIT() asm volatile("cp.async.commit_group;")
#define CP_WAIT1()  asm volatile("cp.async.wait_group 1;")
#define CP_WAIT0()  asm volatile("cp.async.wait_group 0;")

__device__ __forceinline__ void ldmx4(uint32_t* r, uint32_t addr){
    asm volatile("ldmatrix.sync.aligned.m8n8.x4.shared.b16 {%0,%1,%2,%3}, [%4];"
        : "=r"(r[0]), "=r"(r[1]), "=r"(r[2]), "=r"(r[3]) : "r"(addr));
}
__device__ __forceinline__ void ldmx4t(uint32_t* r, uint32_t addr){
    asm volatile("ldmatrix.sync.aligned.m8n8.x4.trans.shared.b16 {%0,%1,%2,%3}, [%4];"
        : "=r"(r[0]), "=r"(r[1]), "=r"(r[2]), "=r"(r[3]) : "r"(addr));
}
__device__ __forceinline__ void mma16816(float* c, const uint32_t* a, const uint32_t* b){
    asm volatile("mma.sync.aligned.m16n8k16.row.col.f32.f16.f16.f32 "
        "{%0,%1,%2,%3}, {%4,%5,%6,%7}, {%8,%9}, {%0,%1,%2,%3};"
        : "+f"(c[0]), "+f"(c[1]), "+f"(c[2]), "+f"(c[3])
        : "r"(a[0]), "r"(a[1]), "r"(a[2]), "r"(a[3]), "r"(b[0]), "r"(b[1]));
}
__device__ __forceinline__ uint32_t pk2f(float a, float b){
    __half2 h = __floats2half2_rn(a, b);
    return *reinterpret_cast<uint32_t*>(&h);
}
__device__ __forceinline__ int rpi(int r, int c){
    int ai = r/7, aj = r%7, bi = c/7, bj = c%7;
    return (ai - bi + 6)*13 + (aj - bj + 6);
}

// ------- prep (weights, bias, Q frags) + conv_x merged, grid 4096x256 -------
__global__ void prep_conv(const float* __restrict__ qkv_w,
                          const float* __restrict__ proj_w,
                          const float* __restrict__ rbt,
                          const float* __restrict__ qg,
                          const float* __restrict__ x)
{
    int idx = blockIdx.x * 256 + threadIdx.x;
    if (idx < 512*256) g_B1[idx] = __float2half_rn(qkv_w[idx]);
    if (idx < 256*256) g_B2[idx] = __float2half_rn(proj_w[idx]);
    if (idx < HEADS*4*7*32) {
        int lane = idx & 31;
        int nt = (idx >> 5) % 7;
        int mt = (idx >> 5) / 7 % 4;
        int h  = idx / (32*7*4);
        int r0 = mt*16 + (lane>>2), r1 = r0 + 8;
        int c0 = nt*8 + 2*(lane&3), c1 = c0 + 1;
        float4 v;
        v.x = (r0 < 49 && c0 < 49) ? rbt[rpi(r0,c0)*HEADS + h]*LOG2E : -1e30f;
        v.y = (r0 < 49 && c1 < 49) ? rbt[rpi(r0,c1)*HEADS + h]*LOG2E : -1e30f;
        v.z = (r1 < 49 && c0 < 49) ? rbt[rpi(r1,c0)*HEADS + h]*LOG2E : -1e30f;
        v.w = (r1 < 49 && c1 < 49) ? rbt[rpi(r1,c1)*HEADS + h]*LOG2E : -1e30f;
        g_biasF[idx] = v;
    }
    if (idx < 64*HEADS*4*2*32) {   // Q fragments, pre-scaled by SCALE*LOG2E
        int lane = idx & 31;
        int kind = (idx >> 5) & 1;
        int mt   = (idx >> 6) & 3;
        int h    = (idx >> 8) & 7;
        int img  = idx >> 11;
        int r = mt*16 + (lane>>2);
        int c2 = 2*(lane&3);
        int db = kind * 16;
        const float qs = SCALE * LOG2E;
        auto qget = [&](int rr, int d) -> float {
            if (rr >= 49) return 0.f;
            return qg[(((size_t)img*HEADS + h)*NTOK + rr)*HDIM + d] * qs;
        };
        uint4 o;
        o.x = pk2f(qget(r,   db+c2),   qget(r,   db+c2+1));
        o.y = pk2f(qget(r+8, db+c2),   qget(r+8, db+c2+1));
        o.z = pk2f(qget(r,   db+c2+8), qget(r,   db+c2+9));
        o.w = pk2f(qget(r+8, db+c2+8), qget(r+8, db+c2+9));
        g_Qf[idx] = o;
    }
    // conv_x: grid-stride over TOKS*64 float4s
    {
        const float4* x4 = (const float4*)x;
        int stride = gridDim.x * 256;
        for (int i = idx; i < TOKS*64; i += stride) {
            float4 v = __ldg(x4 + i);
            *(uint2*)(g_A1 + (size_t)i*4) = make_uint2(pk2f(v.x, v.y), pk2f(v.z, v.w));
        }
    }
}

// ---------------- mma.sync fp16 GEMM: C[128,128] per CTA, K=256 ------------
#define GSTAGE 16384
#define GSMEM  (3*2*GSTAGE)    // 96 KB

template<int NOUT>
__global__ void __launch_bounds__(256, 2)
gemm_k(const float* __restrict__ bias, float* __restrict__ extC)
{
    extern __shared__ char sm[];
    const __half* Ag = (NOUT == 512) ? g_A1 : g_A2;
    const __half* Bg = (NOUT == 512) ? g_B1 : g_B2;

    const int tid = threadIdx.x;
    const int n0 = blockIdx.x * 128;
    const int m0 = blockIdx.y * 128;
    const uint32_t sb = smem_u32(sm);

    auto load_stage = [&](int i, int s){
        const char* Abase = (const char*)Ag + ((size_t)m0*KD + (size_t)i*64)*2;
        const char* Bbase = (const char*)Bg + ((size_t)n0*KD + (size_t)i*64)*2;
        uint32_t sa  = sb + s*2*GSTAGE;
        uint32_t sbB = sa + GSTAGE;
        #pragma unroll
        for (int u = 0; u < 4; u++) {
            int idx = tid + u*256;
            int r = idx >> 3, c16 = idx & 7;
            uint32_t dst = (uint32_t)(r*128 + ((c16 ^ (r & 7))*16));
            cp_async16(sa  + dst, Abase + (size_t)r*(KD*2) + c16*16);
            cp_async16(sbB + dst, Bbase + (size_t)r*(KD*2) + c16*16);
        }
        CP_COMMIT();
    };

    const int w = tid >> 5, lane = tid & 31;
    const int wm = w >> 1, wn = w & 1;
    const int aRow = wm*32 + (lane & 15);
    const int aC16 = (lane >> 4);
    const int bRow = wn*64 + (lane & 7) + ((lane >> 4) << 3);
    const int bC16 = (lane >> 3) & 1;
    const int lc2 = 2*(lane & 3);

    float acc[2][8][4];
    #pragma unroll
    for (int mt = 0; mt < 2; mt++)
        #pragma unroll
        for (int nt = 0; nt < 8; nt++)
            #pragma unroll
            for (int q = 0; q < 4; q++) acc[mt][nt][q] = 0.f;

    load_stage(0, 0);
    load_stage(1, 1);
    int s = 0;
    for (int i = 0; i < NITER; i++) {
        if (i < NITER-1) { CP_WAIT1(); } else { CP_WAIT0(); }
        __syncthreads();
        if (i + 2 < NITER) {
            int s2 = s + 2; if (s2 >= 3) s2 -= 3;
            load_stage(i + 2, s2);
        }
        const uint32_t sa  = sb + s*2*GSTAGE;
        const uint32_t sbB = sa + GSTAGE;
        uint32_t af[4][2][4];
        #pragma unroll
        for (int kk = 0; kk < 4; kk++)
            #pragma unroll
            for (int mt = 0; mt < 2; mt++) {
                int r = aRow + mt*16, c = kk*2 + aC16;
                ldmx4(af[kk][mt], sa + r*128 + ((c ^ (r & 7))*16));
            }
        #pragma unroll
        for (int kk = 0; kk < 4; kk++) {
            #pragma unroll
            for (int np = 0; np < 4; np++) {
                uint32_t bf[4];
                int r = bRow + np*16, c = kk*2 + bC16;
                ldmx4(bf, sbB + r*128 + ((c ^ (r & 7))*16));
                #pragma unroll
                for (int mt = 0; mt < 2; mt++) {
                    mma16816(acc[mt][np*2+0], af[kk][mt], bf+0);
                    mma16816(acc[mt][np*2+1], af[kk][mt], bf+2);
                }
            }
        }
        if (++s >= 3) s -= 3;
    }

    if (NOUT == 256) {
        #pragma unroll
        for (int nt = 0; nt < 8; nt++) {
            int col = n0 + wn*64 + nt*8 + lc2;
            float bx = __ldg(bias + col), by = __ldg(bias + col + 1);
            #pragma unroll
            for (int mt = 0; mt < 2; mt++) {
                int row = m0 + wm*32 + mt*16 + (lane >> 2);
                float2 v0 = make_float2(acc[mt][nt][0] + bx, acc[mt][nt][1] + by);
                float2 v1 = make_float2(acc[mt][nt][2] + bx, acc[mt][nt][3] + by);
                *(float2*)(extC + (size_t)row*NOUT + col)       = v0;
                *(float2*)(extC + (size_t)(row+8)*NOUT + col)   = v1;
            }
        }
    } else {
        // unified K/V epilogue: both hi-only tok-major 64B-row tiles, same swizzle
        const bool isK = (n0 + wn*64) < 256;
        char* arr = isK ? (char*)g_Ks : (char*)g_Vt;
        #pragma unroll
        for (int mt = 0; mt < 2; mt++) {
            int rowb = m0 + wm*32 + mt*16 + (lane >> 2);
            #pragma unroll
            for (int rr = 0; rr < 2; rr++) {
                int r = rowb + rr*8;
                int win = r / 49, tok = r - win*49;
                int key = (tok >> 1) & 3;
                char* base = arr + (size_t)win*(HEADS*4096) + (size_t)tok*64;
                #pragma unroll
                for (int nt = 0; nt < 8; nt++) {
                    int gc = n0 + wn*64 + nt*8 + lc2;
                    float v0 = acc[mt][nt][rr*2]   + __ldg(bias + gc);
                    float v1 = acc[mt][nt][rr*2+1] + __ldg(bias + gc + 1);
                    int c = gc & 255, head = c >> 5, d = c & 31;
                    char* tb = base + head*4096;
                    int chunk = d >> 3, inb = (2*d) & 15;
                    *(uint32_t*)(tb + ((chunk ^ key)*16) + inb) = pk2f(v0, v1);
                }
            }
        }
    }
}

// ---------------- tensor-core attention (fp16, exp2 softmax, no max-pass) ---
#define ASMEM (32768 + 32768)   // K 32KB + V 32KB = 64KB
__global__ void __launch_bounds__(256, 3)
attn_k()
{
    extern __shared__ char sm[];
    const int tid = threadIdx.x, b = blockIdx.x;
    const uint32_t sb = smem_u32(sm);

    {   // zero-fill pad rows 49..63 of every head tile (K and V buffers)
        // 2 buffers x 8 heads x 15 rows x 4 chunks = 960 16B chunks
        for (int u = tid; u < 960; u += 256) {
            int buf = u / 480, i = u - buf*480;
            int head = i / 60, rem = i - head*60;     // 15 rows x 4
            uint32_t off = (uint32_t)(buf*32768 + head*4096 + (49 + (rem>>2))*64 + (rem&3)*16);
            *(uint4*)(sm + off) = make_uint4(0,0,0,0);
        }
        // stage K rows 0..48 (group 0), then V rows 0..48 (group 1)
        const char* srcK = (const char*)g_Ks + (size_t)b*32768;
        const char* srcV = (const char*)g_Vt + (size_t)b*32768;
        #pragma unroll
        for (int u = 0; u < 7; u++) {          // 1568 chunks
            int i = tid + u*256;
            if (i < 1568) {
                int head = i / 196, rem = i - head*196;   // 49 rows x 4
                uint32_t off = (uint32_t)(head*4096 + (rem>>2)*64 + (rem&3)*16);
                cp_async16(sb + off, srcK + off);
            }
        }
        CP_COMMIT();
        #pragma unroll
        for (int u = 0; u < 7; u++) {
            int i = tid + u*256;
            if (i < 1568) {
                int head = i / 196, rem = i - head*196;
                uint32_t off = (uint32_t)(head*4096 + (rem>>2)*64 + (rem&3)*16);
                cp_async16(sb + 32768 + off, srcV + off);
            }
        }
        CP_COMMIT();
        CP_WAIT1();   // K arrived; V still in flight
    }
    __syncthreads();

    const int h = tid >> 5, lane = tid & 31;
    const int img = b >> 6;
    const uint32_t Kt = sb + h*4096;
    const uint32_t Vt = sb + 32768 + h*4096;
    const int lr = lane >> 2, lc2 = 2*(lane & 3);
    const int brow = (lane & 7) + ((lane >> 4) << 3);
    const int bch  = (lane >> 3) & 1;
    const int vrow = lane & 15;
    const int vch  = lane >> 4;

    const uint4*  qf = g_Qf    + ((size_t)(img*HEADS + h)*8)*32 + lane;
    const float4* bf = g_biasF + ((size_t)h*4*7)*32 + lane;

    for (int mt = 0; mt < 4; mt++) {
        uint32_t af[2][4];
        #pragma unroll
        for (int kd = 0; kd < 2; kd++) {
            uint4 v = __ldg(qf + (mt*2 + kd)*32);
            af[kd][0]=v.x; af[kd][1]=v.y; af[kd][2]=v.z; af[kd][3]=v.w;
        }
        float s[8][4];
        #pragma unroll
        for (int nt = 0; nt < 8; nt++)
            #pragma unroll
            for (int j = 0; j < 4; j++) s[nt][j] = 0.f;

        // QK^T in log2 domain (Q pre-scaled by SCALE*log2e)
        #pragma unroll
        for (int np = 0; np < 4; np++) {
            uint32_t kb[2][4];
            int row = np*16 + brow;
            int key = (row >> 1) & 3;
            #pragma unroll
            for (int ch = 0; ch < 2; ch++) {
                int chunk = ch*2 + bch;
                ldmx4(kb[ch], Kt + row*64 + ((chunk ^ key)*16));
            }
            float* s0 = s[2*np]; float* s1 = s[2*np+1];
            mma16816(s0, af[0], kb[0]+0); mma16816(s1, af[0], kb[0]+2);
            mma16816(s0, af[1], kb[1]+0); mma16816(s1, af[1], kb[1]+2);
        }

        // softmax (no max-pass: scores bounded); p = exp2(s + bias2)
        float den0 = 0.f, den1 = 0.f;
        #pragma unroll
        for (int nt = 0; nt < 7; nt++) {
            float4 t = __ldg(bf + (mt*7 + nt)*32);
            s[nt][0] = exp2f(s[nt][0] + t.x); den0 += s[nt][0];
            s[nt][1] = exp2f(s[nt][1] + t.y); den0 += s[nt][1];
            s[nt][2] = exp2f(s[nt][2] + t.z); den1 += s[nt][2];
            s[nt][3] = exp2f(s[nt][3] + t.w); den1 += s[nt][3];
        }
        den0 += __shfl_xor_sync(0xFFFFFFFF, den0, 1);
        den0 += __shfl_xor_sync(0xFFFFFFFF, den0, 2);
        den1 += __shfl_xor_sync(0xFFFFFFFF, den1, 1);
        den1 += __shfl_xor_sync(0xFFFFFFFF, den1, 2);
        float rinv0 = 1.f / den0, rinv1 = 1.f / den1;

        // P -> A fragments (fp16, packed cvt)
        uint32_t ph[4][4];
        #pragma unroll
        for (int ks = 0; ks < 4; ks++) {
            #pragma unroll
            for (int half_ = 0; half_ < 2; half_++) {
                int nt = 2*ks + half_;
                if (nt < 7) {
                    ph[ks][half_*2+0] = pk2f(s[nt][0], s[nt][1]);
                    ph[ks][half_*2+1] = pk2f(s[nt][2], s[nt][3]);
                } else {
                    ph[ks][half_*2] = 0; ph[ks][half_*2+1] = 0;
                }
            }
        }

        // before first PV, make sure V staging landed
        if (mt == 0) { CP_WAIT0(); __syncthreads(); }

        // PV: p x v, V via ldmatrix.trans from tok-major tiles
        float o[4][4];
        #pragma unroll
        for (int nt = 0; nt < 4; nt++)
            #pragma unroll
            for (int j = 0; j < 4; j++) o[nt][j] = 0.f;
        #pragma unroll
        for (int ks = 0; ks < 4; ks++) {
            int row = ks*16 + vrow;
            int key = (row >> 1) & 3;
            #pragma unroll
            for (int nh = 0; nh < 2; nh++) {
                uint32_t vh[4];
                int chunk = nh*2 + vch;
                ldmx4t(vh, Vt + row*64 + ((chunk ^ key)*16));
                mma16816(o[2*nh+0], ph[ks], vh+0);
                mma16816(o[2*nh+1], ph[ks], vh+2);
            }
        }

        // store to g_A2 (fp16, [t][256]), packed cvt
        int r0 = mt*16 + lr, r1 = r0 + 8;
        if (r0 < 49) {
            __half* dst = g_A2 + ((size_t)b*NTOK + r0)*KD;
            #pragma unroll
            for (int nt = 0; nt < 4; nt++) {
                int gc = h*HDIM + nt*8 + lc2;
                *(uint32_t*)(dst + gc) = pk2f(o[nt][0]*rinv0, o[nt][1]*rinv0);
            }
        }
        if (r1 < 49) {
            __half* dst = g_A2 + ((size_t)b*NTOK + r1)*KD;
            #pragma unroll
            for (int nt = 0; nt < 4; nt++) {
                int gc = h*HDIM + nt*8 + lc2;
                *(uint32_t*)(dst + gc) = pk2f(o[nt][2]*rinv1, o[nt][3]*rinv1);
            }
        }
    }
}

// ---------------- launch ----------------
extern "C" void kernel_launch(void* const* d_in, const int* in_sizes, int n_in,
                              void* d_out, int out_size)
{
    const float* x      = (const float*)d_in[0];
    const float* qg     = (const float*)d_in[1];
    const float* qkv_w  = (const float*)d_in[2];
    const float* qkv_b  = (const float*)d_in[3];
    const float* proj_w = (const float*)d_in[4];
    const float* proj_b = (const float*)d_in[5];
    const float* rbt    = (const float*)d_in[6];
    float* out = (float*)d_out;
    (void)in_sizes; (void)n_in; (void)out_size;

    cudaFuncSetAttribute(gemm_k<512>, cudaFuncAttributeMaxDynamicSharedMemorySize, GSMEM);
    cudaFuncSetAttribute(gemm_k<256>, cudaFuncAttributeMaxDynamicSharedMemorySize, GSMEM);
    cudaFuncSetAttribute(attn_k,      cudaFuncAttributeMaxDynamicSharedMemorySize, ASMEM);

    prep_conv<<<4096, 256>>>(qkv_w, proj_w, rbt, qg, x);
    {
        dim3 g1(4, TOKS/128);
        gemm_k<512><<<g1, 256, GSMEM>>>(qkv_b, nullptr);
    }
    attn_k<<<BWIN, 256, ASMEM>>>();
    {
        dim3 g2(2, TOKS/128);
        gemm_k<256><<<g2, 256, GSMEM>>>(proj_b, out);
    }
}

// round 14
// speedup vs baseline: 1.0941x; 1.0277x over previous
#include <cuda_runtime.h>
#include <cuda_fp16.h>
#include <cstdint>
#include <math.h>

#define NTOK   49
#define CDIM   256
#define HEADS  8
#define HDIM   32
#define BWIN   4096
#define TOKS   (BWIN*NTOK)          // 200704 = 1568 * 128
#define KD     256                  // plain fp16
#define NITER  4                    // K/64
#define SCALE  0.17677669529663688f
#define LOG2E  1.4426950408889634f

// ---------------- scratch (device globals; no allocs) ----------------
__device__ __half g_A1[(size_t)TOKS*KD];   // fp16(x)   [t][256]
__device__ __half g_A2[(size_t)TOKS*KD];   // attn-out  [t][256]
__device__ __half g_B1[512*KD];            // fp16(qkv_w)
__device__ __half g_B2[256*KD];            // fp16(proj_w)
// K and V tiles: [win][head] 64 tok-rows x 64B (32 fp16), swizzle key (tok>>1)&3. pads stay 0.
__device__ unsigned char g_Ks[(size_t)BWIN*HEADS*4096];
__device__ unsigned char g_Vt[(size_t)BWIN*HEADS*4096];
// Q fragments: [img][head][mtile 4][kind 2][lane 32] uint4 (pre-scaled by SCALE*LOG2E)
__device__ uint4  g_Qf[64*HEADS*4*2*32];
// bias in C-fragment layout, x LOG2E, mask folded: [head][mtile 4][ntile 7][lane 32] float4
__device__ float4 g_biasF[HEADS*4*7*32];

// ---------------- helpers ----------------
__device__ __forceinline__ uint32_t smem_u32(const void* p){
    uint32_t a;
    asm("{ .reg .u64 t; cvta.to.shared.u64 t, %1; cvt.u32.u64 %0, t; }" : "=r"(a) : "l"(p));
    return a;
}
__device__ __forceinline__ void cp_async16(uint32_t dst, const void* src){
    asm volatile("cp.async.cg.shared.global [%0], [%1], 16;" :: "r"(dst), "l"(src));
}
#define CP_COMMIT() asm volatile("cp.async.commit_group;")
#define CP_WAIT1()  asm volatile("cp.async.wait_group 1;")
#define CP_WAIT0()  asm volatile("cp.async.wait_group 0;")

__device__ __forceinline__ void ldmx4(uint32_t* r, uint32_t addr){
    asm volatile("ldmatrix.sync.aligned.m8n8.x4.shared.b16 {%0,%1,%2,%3}, [%4];"
        : "=r"(r[0]), "=r"(r[1]), "=r"(r[2]), "=r"(r[3]) : "r"(addr));
}
__device__ __forceinline__ void ldmx4t(uint32_t* r, uint32_t addr){
    asm volatile("ldmatrix.sync.aligned.m8n8.x4.trans.shared.b16 {%0,%1,%2,%3}, [%4];"
        : "=r"(r[0]), "=r"(r[1]), "=r"(r[2]), "=r"(r[3]) : "r"(addr));
}
__device__ __forceinline__ void mma16816(float* c, const uint32_t* a, const uint32_t* b){
    asm volatile("mma.sync.aligned.m16n8k16.row.col.f32.f16.f16.f32 "
        "{%0,%1,%2,%3}, {%4,%5,%6,%7}, {%8,%9}, {%0,%1,%2,%3};"
        : "+f"(c[0]), "+f"(c[1]), "+f"(c[2]), "+f"(c[3])
        : "r"(a[0]), "r"(a[1]), "r"(a[2]), "r"(a[3]), "r"(b[0]), "r"(b[1]));
}
__device__ __forceinline__ uint32_t pk2f(float a, float b){
    __half2 h = __floats2half2_rn(a, b);
    return *reinterpret_cast<uint32_t*>(&h);
}
__device__ __forceinline__ int rpi(int r, int c){
    int ai = r/7, aj = r%7, bi = c/7, bj = c%7;
    return (ai - bi + 6)*13 + (aj - bj + 6);
}

// ------- prep (weights, bias, Q frags) + conv_x merged, grid 4096x256 -------
__global__ void prep_conv(const float* __restrict__ qkv_w,
                          const float* __restrict__ proj_w,
                          const float* __restrict__ rbt,
                          const float* __restrict__ qg,
                          const float* __restrict__ x)
{
    int idx = blockIdx.x * 256 + threadIdx.x;
    if (idx < 512*256) g_B1[idx] = __float2half_rn(qkv_w[idx]);
    if (idx < 256*256) g_B2[idx] = __float2half_rn(proj_w[idx]);
    if (idx < HEADS*4*7*32) {
        int lane = idx & 31;
        int nt = (idx >> 5) % 7;
        int mt = (idx >> 5) / 7 % 4;
        int h  = idx / (32*7*4);
        int r0 = mt*16 + (lane>>2), r1 = r0 + 8;
        int c0 = nt*8 + 2*(lane&3), c1 = c0 + 1;
        float4 v;
        v.x = (r0 < 49 && c0 < 49) ? rbt[rpi(r0,c0)*HEADS + h]*LOG2E : -1e30f;
        v.y = (r0 < 49 && c1 < 49) ? rbt[rpi(r0,c1)*HEADS + h]*LOG2E : -1e30f;
        v.z = (r1 < 49 && c0 < 49) ? rbt[rpi(r1,c0)*HEADS + h]*LOG2E : -1e30f;
        v.w = (r1 < 49 && c1 < 49) ? rbt[rpi(r1,c1)*HEADS + h]*LOG2E : -1e30f;
        g_biasF[idx] = v;
    }
    if (idx < 64*HEADS*4*2*32) {   // Q fragments, pre-scaled by SCALE*LOG2E
        int lane = idx & 31;
        int kind = (idx >> 5) & 1;
        int mt   = (idx >> 6) & 3;
        int h    = (idx >> 8) & 7;
        int img  = idx >> 11;
        int r = mt*16 + (lane>>2);
        int c2 = 2*(lane&3);
        int db = kind * 16;
        const float qs = SCALE * LOG2E;
        auto qget = [&](int rr, int d) -> float {
            if (rr >= 49) return 0.f;
            return qg[(((size_t)img*HEADS + h)*NTOK + rr)*HDIM + d] * qs;
        };
        uint4 o;
        o.x = pk2f(qget(r,   db+c2),   qget(r,   db+c2+1));
        o.y = pk2f(qget(r+8, db+c2),   qget(r+8, db+c2+1));
        o.z = pk2f(qget(r,   db+c2+8), qget(r,   db+c2+9));
        o.w = pk2f(qget(r+8, db+c2+8), qget(r+8, db+c2+9));
        g_Qf[idx] = o;
    }
    // conv_x: grid-stride over TOKS*64 float4s
    {
        const float4* x4 = (const float4*)x;
        int stride = gridDim.x * 256;
        for (int i = idx; i < TOKS*64; i += stride) {
            float4 v = __ldg(x4 + i);
            *(uint2*)(g_A1 + (size_t)i*4) = make_uint2(pk2f(v.x, v.y), pk2f(v.z, v.w));
        }
    }
}

// ------- mma.sync fp16 GEMM, B-resident: C[128,128] per CTA, K=256 ---------
// SMEM: [0,64K) B full tile (4 k-chunks x 16KB) ; [64K, 64K+3*16K) A stages
#define GA_OFF 65536
#define GSMEM  (65536 + 3*16384)   // 112 KB

template<int NOUT>
__global__ void __launch_bounds__(256, 2)
gemm_k(const float* __restrict__ bias, float* __restrict__ extC)
{
    extern __shared__ char sm[];
    const __half* Ag = (NOUT == 512) ? g_A1 : g_A2;
    const __half* Bg = (NOUT == 512) ? g_B1 : g_B2;

    const int tid = threadIdx.x;
    const int n0 = blockIdx.x * 128;
    const int m0 = blockIdx.y * 128;
    const uint32_t sb = smem_u32(sm);

    // B: load the whole 128x256 tile once (64KB, 4096 16B chunks)
    {
        const char* Bbase = (const char*)Bg + (size_t)n0*KD*2;
        #pragma unroll
        for (int u = 0; u < 16; u++) {
            int idx = tid + u*256;          // 0..4095
            int kc = idx >> 10;             // k-chunk 0..3
            int rem = idx & 1023;
            int r = rem >> 3, c16 = rem & 7;
            uint32_t dst = (uint32_t)(kc*16384 + r*128 + ((c16 ^ (r & 7))*16));
            cp_async16(sb + dst, Bbase + (size_t)r*(KD*2) + kc*128 + c16*16);
        }
        CP_COMMIT();
    }

    auto load_a = [&](int i, int s){
        const char* Abase = (const char*)Ag + ((size_t)m0*KD + (size_t)i*64)*2;
        uint32_t sa = sb + GA_OFF + s*16384;
        #pragma unroll
        for (int u = 0; u < 4; u++) {
            int idx = tid + u*256;
            int r = idx >> 3, c16 = idx & 7;
            uint32_t dst = (uint32_t)(r*128 + ((c16 ^ (r & 7))*16));
            cp_async16(sa + dst, Abase + (size_t)r*(KD*2) + c16*16);
        }
        CP_COMMIT();
    };

    const int w = tid >> 5, lane = tid & 31;
    const int wm = w >> 1, wn = w & 1;
    const int aRow = wm*32 + (lane & 15);
    const int aC16 = (lane >> 4);
    const int bRow = wn*64 + (lane & 7) + ((lane >> 4) << 3);
    const int bC16 = (lane >> 3) & 1;
    const int lc2 = 2*(lane & 3);

    float acc[2][8][4];
    #pragma unroll
    for (int mt = 0; mt < 2; mt++)
        #pragma unroll
        for (int nt = 0; nt < 8; nt++)
            #pragma unroll
            for (int q = 0; q < 4; q++) acc[mt][nt][q] = 0.f;

    load_a(0, 0);
    load_a(1, 1);
    int s = 0;
    for (int i = 0; i < NITER; i++) {
        // pending groups: i=0:{B,A0,A1} wait1->B,A0 ; i=1:{A1,A2} wait1->A1 ; ...
        if (i < NITER-1) { CP_WAIT1(); } else { CP_WAIT0(); }
        __syncthreads();
        if (i + 2 < NITER) {
            int s2 = s + 2; if (s2 >= 3) s2 -= 3;
            load_a(i + 2, s2);
        }
        const uint32_t sa  = sb + GA_OFF + s*16384;
        const uint32_t sbB = sb + i*16384;          // resident B, k-chunk i
        uint32_t af[4][2][4];
        #pragma unroll
        for (int kk = 0; kk < 4; kk++)
            #pragma unroll
            for (int mt = 0; mt < 2; mt++) {
                int r = aRow + mt*16, c = kk*2 + aC16;
                ldmx4(af[kk][mt], sa + r*128 + ((c ^ (r & 7))*16));
            }
        #pragma unroll
        for (int kk = 0; kk < 4; kk++) {
            #pragma unroll
            for (int np = 0; np < 4; np++) {
                uint32_t bf[4];
                int r = bRow + np*16, c = kk*2 + bC16;
                ldmx4(bf, sbB + r*128 + ((c ^ (r & 7))*16));
                #pragma unroll
                for (int mt = 0; mt < 2; mt++) {
                    mma16816(acc[mt][np*2+0], af[kk][mt], bf+0);
                    mma16816(acc[mt][np*2+1], af[kk][mt], bf+2);
                }
            }
        }
        if (++s >= 3) s -= 3;
    }

    if (NOUT == 256) {
        #pragma unroll
        for (int nt = 0; nt < 8; nt++) {
            int col = n0 + wn*64 + nt*8 + lc2;
            float bx = __ldg(bias + col), by = __ldg(bias + col + 1);
            #pragma unroll
            for (int mt = 0; mt < 2; mt++) {
                int row = m0 + wm*32 + mt*16 + (lane >> 2);
                float2 v0 = make_float2(acc[mt][nt][0] + bx, acc[mt][nt][1] + by);
                float2 v1 = make_float2(acc[mt][nt][2] + bx, acc[mt][nt][3] + by);
                *(float2*)(extC + (size_t)row*NOUT + col)       = v0;
                *(float2*)(extC + (size_t)(row+8)*NOUT + col)   = v1;
            }
        }
    } else {
        // unified K/V epilogue: both hi-only tok-major 64B-row tiles, same swizzle
        const bool isK = (n0 + wn*64) < 256;
        char* arr = isK ? (char*)g_Ks : (char*)g_Vt;
        #pragma unroll
        for (int mt = 0; mt < 2; mt++) {
            int rowb = m0 + wm*32 + mt*16 + (lane >> 2);
            #pragma unroll
            for (int rr = 0; rr < 2; rr++) {
                int r = rowb + rr*8;
                int win = r / 49, tok = r - win*49;
                int key = (tok >> 1) & 3;
                char* base = arr + (size_t)win*(HEADS*4096) + (size_t)tok*64;
                #pragma unroll
                for (int nt = 0; nt < 8; nt++) {
                    int gc = n0 + wn*64 + nt*8 + lc2;
                    float v0 = acc[mt][nt][rr*2]   + __ldg(bias + gc);
                    float v1 = acc[mt][nt][rr*2+1] + __ldg(bias + gc + 1);
                    int c = gc & 255, head = c >> 5, d = c & 31;
                    char* tb = base + head*4096;
                    int chunk = d >> 3, inb = (2*d) & 15;
                    *(uint32_t*)(tb + ((chunk ^ key)*16) + inb) = pk2f(v0, v1);
                }
            }
        }
    }
}

// ---------------- tensor-core attention (fp16, exp2 softmax, no max-pass) ---
#define ASMEM (32768 + 32768)   // K 32KB + V 32KB = 64KB
__global__ void __launch_bounds__(256, 3)
attn_k()
{
    extern __shared__ char sm[];
    const int tid = threadIdx.x, b = blockIdx.x;
    const uint32_t sb = smem_u32(sm);

    {   // zero-fill pad rows 49..63 of every head tile (K and V buffers)
        for (int u = tid; u < 960; u += 256) {
            int buf = u / 480, i = u - buf*480;
            int head = i / 60, rem = i - head*60;
            uint32_t off = (uint32_t)(buf*32768 + head*4096 + (49 + (rem>>2))*64 + (rem&3)*16);
            *(uint4*)(sm + off) = make_uint4(0,0,0,0);
        }
        // stage K rows 0..48 (group 0), then V rows 0..48 (group 1)
        const char* srcK = (const char*)g_Ks + (size_t)b*32768;
        const char* srcV = (const char*)g_Vt + (size_t)b*32768;
        #pragma unroll
        for (int u = 0; u < 7; u++) {
            int i = tid + u*256;
            if (i < 1568) {
                int head = i / 196, rem = i - head*196;
                uint32_t off = (uint32_t)(head*4096 + (rem>>2)*64 + (rem&3)*16);
                cp_async16(sb + off, srcK + off);
            }
        }
        CP_COMMIT();
        #pragma unroll
        for (int u = 0; u < 7; u++) {
            int i = tid + u*256;
            if (i < 1568) {
                int head = i / 196, rem = i - head*196;
                uint32_t off = (uint32_t)(head*4096 + (rem>>2)*64 + (rem&3)*16);
                cp_async16(sb + 32768 + off, srcV + off);
            }
        }
        CP_COMMIT();
        CP_WAIT1();   // K arrived; V still in flight
    }
    __syncthreads();

    const int h = tid >> 5, lane = tid & 31;
    const int img = b >> 6;
    const uint32_t Kt = sb + h*4096;
    const uint32_t Vt = sb + 32768 + h*4096;
    const int lr = lane >> 2, lc2 = 2*(lane & 3);
    const int brow = (lane & 7) + ((lane >> 4) << 3);
    const int bch  = (lane >> 3) & 1;
    const int vrow = lane & 15;
    const int vch  = lane >> 4;

    const uint4*  qf = g_Qf    + ((size_t)(img*HEADS + h)*8)*32 + lane;
    const float4* bf = g_biasF + ((size_t)h*4*7)*32 + lane;

    for (int mt = 0; mt < 4; mt++) {
        uint32_t af[2][4];
        #pragma unroll
        for (int kd = 0; kd < 2; kd++) {
            uint4 v = __ldg(qf + (mt*2 + kd)*32);
            af[kd][0]=v.x; af[kd][1]=v.y; af[kd][2]=v.z; af[kd][3]=v.w;
        }
        float s[8][4];
        #pragma unroll
        for (int nt = 0; nt < 8; nt++)
            #pragma unroll
            for (int j = 0; j < 4; j++) s[nt][j] = 0.f;

        // QK^T in log2 domain (Q pre-scaled by SCALE*log2e)
        #pragma unroll
        for (int np = 0; np < 4; np++) {
            uint32_t kb[2][4];
            int row = np*16 + brow;
            int key = (row >> 1) & 3;
            #pragma unroll
            for (int ch = 0; ch < 2; ch++) {
                int chunk = ch*2 + bch;
                ldmx4(kb[ch], Kt + row*64 + ((chunk ^ key)*16));
            }
            float* s0 = s[2*np]; float* s1 = s[2*np+1];
            mma16816(s0, af[0], kb[0]+0); mma16816(s1, af[0], kb[0]+2);
            mma16816(s0, af[1], kb[1]+0); mma16816(s1, af[1], kb[1]+2);
        }

        // softmax (no max-pass: scores bounded); p = exp2(s + bias2)
        float den0 = 0.f, den1 = 0.f;
        #pragma unroll
        for (int nt = 0; nt < 7; nt++) {
            float4 t = __ldg(bf + (mt*7 + nt)*32);
            s[nt][0] = exp2f(s[nt][0] + t.x); den0 += s[nt][0];
            s[nt][1] = exp2f(s[nt][1] + t.y); den0 += s[nt][1];
            s[nt][2] = exp2f(s[nt][2] + t.z); den1 += s[nt][2];
            s[nt][3] = exp2f(s[nt][3] + t.w); den1 += s[nt][3];
        }
        den0 += __shfl_xor_sync(0xFFFFFFFF, den0, 1);
        den0 += __shfl_xor_sync(0xFFFFFFFF, den0, 2);
        den1 += __shfl_xor_sync(0xFFFFFFFF, den1, 1);
        den1 += __shfl_xor_sync(0xFFFFFFFF, den1, 2);
        float rinv0 = 1.f / den0, rinv1 = 1.f / den1;

        // P -> A fragments (fp16, packed cvt)
        uint32_t ph[4][4];
        #pragma unroll
        for (int ks = 0; ks < 4; ks++) {
            #pragma unroll
            for (int half_ = 0; half_ < 2; half_++) {
                int nt = 2*ks + half_;
                if (nt < 7) {
                    ph[ks][half_*2+0] = pk2f(s[nt][0], s[nt][1]);
                    ph[ks][half_*2+1] = pk2f(s[nt][2], s[nt][3]);
                } else {
                    ph[ks][half_*2] = 0; ph[ks][half_*2+1] = 0;
                }
            }
        }

        // before first PV, make sure V staging landed
        if (mt == 0) { CP_WAIT0(); __syncthreads(); }

        // PV: p x v, V via ldmatrix.trans from tok-major tiles
        float o[4][4];
        #pragma unroll
        for (int nt = 0; nt < 4; nt++)
            #pragma unroll
            for (int j = 0; j < 4; j++) o[nt][j] = 0.f;
        #pragma unroll
        for (int ks = 0; ks < 4; ks++) {
            int row = ks*16 + vrow;
            int key = (row >> 1) & 3;
            #pragma unroll
            for (int nh = 0; nh < 2; nh++) {
                uint32_t vh[4];
                int chunk = nh*2 + vch;
                ldmx4t(vh, Vt + row*64 + ((chunk ^ key)*16));
                mma16816(o[2*nh+0], ph[ks], vh+0);
                mma16816(o[2*nh+1], ph[ks], vh+2);
            }
        }

        // store to g_A2 (fp16, [t][256]), packed cvt
        int r0 = mt*16 + lr, r1 = r0 + 8;
        if (r0 < 49) {
            __half* dst = g_A2 + ((size_t)b*NTOK + r0)*KD;
            #pragma unroll
            for (int nt = 0; nt < 4; nt++) {
                int gc = h*HDIM + nt*8 + lc2;
                *(uint32_t*)(dst + gc) = pk2f(o[nt][0]*rinv0, o[nt][1]*rinv0);
            }
        }
        if (r1 < 49) {
            __half* dst = g_A2 + ((size_t)b*NTOK + r1)*KD;
            #pragma unroll
            for (int nt = 0; nt < 4; nt++) {
                int gc = h*HDIM + nt*8 + lc2;
                *(uint32_t*)(dst + gc) = pk2f(o[nt][2]*rinv1, o[nt][3]*rinv1);
            }
        }
    }
}

// ---------------- launch ----------------
extern "C" void kernel_launch(void* const* d_in, const int* in_sizes, int n_in,
                              void* d_out, int out_size)
{
    const float* x      = (const float*)d_in[0];
    const float* qg     = (const float*)d_in[1];
    const float* qkv_w  = (const float*)d_in[2];
    const float* qkv_b  = (const float*)d_in[3];
    const float* proj_w = (const float*)d_in[4];
    const float* proj_b = (const float*)d_in[5];
    const float* rbt    = (const float*)d_in[6];
    float* out = (float*)d_out;
    (void)in_sizes; (void)n_in; (void)out_size;

    cudaFuncSetAttribute(gemm_k<512>, cudaFuncAttributeMaxDynamicSharedMemorySize, GSMEM);
    cudaFuncSetAttribute(gemm_k<256>, cudaFuncAttributeMaxDynamicSharedMemorySize, GSMEM);
    cudaFuncSetAttribute(attn_k,      cudaFuncAttributeMaxDynamicSharedMemorySize, ASMEM);

    prep_conv<<<4096, 256>>>(qkv_w, proj_w, rbt, qg, x);
    {
        dim3 g1(4, TOKS/128);
        gemm_k<512><<<g1, 256, GSMEM>>>(qkv_b, nullptr);
    }
    attn_k<<<BWIN, 256, ASMEM>>>();
    {
        dim3 g2(2, TOKS/128);
        gemm_k<256><<<g2, 256, GSMEM>>>(proj_b, out);
    }
}